// round 16
// baseline (speedup 1.0000x reference)
#include <cuda_runtime.h>
#include <cuda_fp16.h>
#include <math.h>
#include <stdint.h>

#define Bz 4
#define T 2048
#define C 1024
#define NH 16
#define HS 64
#define M (Bz*T)

// ---------------- scratch (__device__ globals) -------------------------------
// A-pack (fp16 m16n8k16 A-frags): uint4[((mtile*64 + kk)*8 + m16)*32 + lane]
// B-pack (fp16 B-frags):          uint2[((ntile*64 + kk)*16 + n8)*32 + lane]
// K/V-pack (attention B-frags, per b*h and 64-key tile):
//   uint2[(((bh*32 + tile)*4 + kk)*256) + n8*32 + lane]
__device__ uint4 g_x  [64*64*8*32];
__device__ uint4 g_att[64*64*8*32];
__device__ uint2 g_wq [8*64*16*32];
__device__ uint2 g_wk [8*64*16*32];
__device__ uint2 g_wv [8*64*16*32];
__device__ uint2 g_wp [8*64*16*32];
__device__ float  g_q[Bz*NH*T*HS];      // [B,NH,T,HS] fp32, RoPE'd
__device__ uint2  g_kp[64*32*1024];     // K packed (16 MB)
__device__ uint2  g_vp[64*32*1024];     // V packed (16 MB)

// ---------------- helpers ----------------------------------------------------
__device__ __forceinline__ uint32_t h2(float a, float b) {
    __half2 h = __floats2half2_rn(a, b);
    return *(uint32_t*)&h;
}
__device__ __forceinline__ uint32_t h2exp2u(float a, float b) {
    __half2 h = h2exp2(__floats2half2_rn(a, b));
    return *(uint32_t*)&h;
}

__device__ __forceinline__ void mma_f16(float4 &d,
    uint32_t a0, uint32_t a1, uint32_t a2, uint32_t a3,
    uint32_t b0, uint32_t b1)
{
    asm volatile(
        "mma.sync.aligned.m16n8k16.row.col.f32.f16.f16.f32 "
        "{%0,%1,%2,%3}, {%4,%5,%6,%7}, {%8,%9}, {%0,%1,%2,%3};\n"
        : "+f"(d.x), "+f"(d.y), "+f"(d.z), "+f"(d.w)
        : "r"(a0), "r"(a1), "r"(a2), "r"(a3), "r"(b0), "r"(b1));
}

__device__ __forceinline__ void cp16b(void* sdst, const void* gsrc) {
    uint32_t s = (uint32_t)__cvta_generic_to_shared(sdst);
    asm volatile("cp.async.cg.shared.global [%0], [%1], 16;" :: "r"(s), "l"(gsrc));
}
#define CP_COMMIT()  asm volatile("cp.async.commit_group;" ::: "memory")
#define CP_WAIT(N)   asm volatile("cp.async.wait_group %0;" :: "n"(N) : "memory")

// ---------------- prep: pack X into A-frag fp16 ------------------------------
__global__ void cvt_x(const float* __restrict__ x) {
    int idx = blockIdx.x * 256 + threadIdx.x;
    int lane = idx & 31, m16 = (idx >> 5) & 7, kk = (idx >> 8) & 63, mtile = idx >> 14;
    int g = lane >> 2, t = lane & 3;
    const float* p0 = x + (size_t)(mtile * 128 + m16 * 16 + g) * C + kk * 16 + 2 * t;
    const float* p1 = p0 + 8 * C;
    float2 v00 = *(const float2*)p0;
    float2 v10 = *(const float2*)p1;
    float2 v01 = *(const float2*)(p0 + 8);
    float2 v11 = *(const float2*)(p1 + 8);
    g_x[idx] = make_uint4(h2(v00.x, v00.y), h2(v10.x, v10.y),
                          h2(v01.x, v01.y), h2(v11.x, v11.y));
}

// ---------------- prep: pack all 4 W into B-frag fp16 (one launch) -----------
__global__ void wtr_all(const float* __restrict__ wq, const float* __restrict__ wk,
                        const float* __restrict__ wv, const float* __restrict__ wp)
{
    int sel = blockIdx.x >> 10;
    const float* w = (sel == 0) ? wq : (sel == 1) ? wk : (sel == 2) ? wv : wp;
    uint2* dst = (sel == 0) ? g_wq : (sel == 1) ? g_wk : (sel == 2) ? g_wv : g_wp;
    int idx = (blockIdx.x & 1023) * 256 + threadIdx.x;
    int lane = idx & 31, n8 = (idx >> 5) & 15, kk = (idx >> 9) & 63, ntile = idx >> 15;
    int g = lane >> 2, t = lane & 3;
    int n = ntile * 128 + n8 * 8 + g;
    const float* p = w + (size_t)(kk * 16 + 2 * t) * C + n;
    dst[idx] = make_uint2(h2(p[0], p[C]), h2(p[8 * C], p[9 * C]));
}

// ---------------- GEMM: fp16 k16, BK=64, 3-stage cp.async ring ---------------
#define GSTG 32768
#define GEMM_SMEM (3 * GSTG)   // 98304 B

template<int QKV>
__global__ __launch_bounds__(256, 2)
void gemm_tc(const float* __restrict__ b0p,
             const float* __restrict__ b1p,
             const float* __restrict__ b2p,
             float* __restrict__ outp)
{
    extern __shared__ char smb[];

    const uint4* Apk;
    const uint2* Bpk;
    const float* bias;
    int sel, ntile;
    if (QKV) {
        Apk = g_x;
        sel = blockIdx.x >> 3;
        ntile = blockIdx.x & 7;
        Bpk  = (sel == 0) ? g_wq : (sel == 1) ? g_wk : g_wv;
        bias = (sel == 0) ? b0p  : (sel == 1) ? b1p  : b2p;
    } else {
        Apk = g_att;
        sel = 3;
        ntile = blockIdx.x;
        Bpk = g_wp; bias = b0p;
    }
    const int mtile = blockIdx.y;
    const int tileM = mtile * 128;
    const int tileN = ntile * 128;

    const int tid   = threadIdx.x;
    const int lane  = tid & 31;
    const int warp  = tid >> 5;
    const int warpM = warp >> 2;
    const int warpN = warp & 3;
    const int g     = lane >> 2;
    const int t     = lane & 3;

    float4 acc[4][4];
    #pragma unroll
    for (int i = 0; i < 4; i++)
        #pragma unroll
        for (int j = 0; j < 4; j++)
            acc[i][j] = make_float4(0.f, 0.f, 0.f, 0.f);

    auto pref = [&](int s, int j) {
        char* As = smb + s * GSTG;
        char* Bs = As + 16384;
        const char* ap = (const char*)(Apk + ((size_t)mtile * 64 + 4 * j) * 256);
        const char* bp = (const char*)(Bpk + ((size_t)ntile * 64 + 4 * j) * 512);
        #pragma unroll
        for (int i = 0; i < 4; i++) {
            int o = (tid + i * 256) * 16;
            cp16b(As + o, ap + o);
            cp16b(Bs + o, bp + o);
        }
    };

    pref(0, 0); CP_COMMIT();
    pref(1, 1); CP_COMMIT();

    for (int j = 0; j < 16; j++) {
        if (j < 15) { CP_WAIT(1); } else { CP_WAIT(0); }
        __syncthreads();
        if (j + 2 < 16) { pref((j + 2) % 3, j + 2); CP_COMMIT(); }

        const uint4* As4 = (const uint4*)(smb + (j % 3) * GSTG);
        const uint2* Bs2 = (const uint2*)(smb + (j % 3) * GSTG + 16384);

        #pragma unroll
        for (int kk2 = 0; kk2 < 4; kk2++) {
            uint4 af[4];
            uint2 bf[4];
            #pragma unroll
            for (int mf = 0; mf < 4; mf++)
                af[mf] = As4[(kk2 * 8 + warpM * 4 + mf) * 32 + lane];
            #pragma unroll
            for (int nf = 0; nf < 4; nf++)
                bf[nf] = Bs2[(kk2 * 16 + warpN * 4 + nf) * 32 + lane];
            #pragma unroll
            for (int mf = 0; mf < 4; mf++)
                #pragma unroll
                for (int nf = 0; nf < 4; nf++)
                    mma_f16(acc[mf][nf], af[mf].x, af[mf].y, af[mf].z, af[mf].w,
                            bf[nf].x, bf[nf].y);
        }
    }

    // epilogue
    #pragma unroll
    for (int nf = 0; nf < 4; nf++) {
        const int n0 = tileN + warpN * 32 + nf * 8 + t * 2;
        const float bv0 = bias[n0];
        const float bv1 = bias[n0 + 1];
        float inv = 0.f;
        if (QKV) {
            const int ip = (n0 & 63) >> 1;
            inv = powf(10000.0f, -(float)ip / 32.0f);
        }
        #pragma unroll
        for (int mf = 0; mf < 4; mf++) {
            float4 a = acc[mf][nf];
            const int r0 = tileM + warpM * 64 + mf * 16 + g;
            float x0 = a.x + bv0, x1 = a.y + bv1;
            float y0 = a.z + bv0, y1 = a.w + bv1;
            if (!QKV) {
                *(float2*)&outp[(size_t)r0 * C + n0]       = make_float2(x0, x1);
                *(float2*)&outp[(size_t)(r0 + 8) * C + n0] = make_float2(y0, y1);
            } else {
                const int bb = r0 / T;
                const int t0 = r0 % T;
                const int h  = n0 >> 6;
                const int d0 = n0 & 63;
                const int bh = bb * NH + h;
                if (sel < 2) {
                    float sn, cs;
                    sincosf((float)t0 * inv, &sn, &cs);
                    float u0 = x0 * cs - x1 * sn;
                    float u1 = x0 * sn + x1 * cs;
                    x0 = u0; x1 = u1;
                    sincosf((float)(t0 + 8) * inv, &sn, &cs);
                    float w0 = y0 * cs - y1 * sn;
                    float w1 = y0 * sn + y1 * cs;
                    y0 = w0; y1 = w1;
                }
                if (sel == 0) {
                    float* dst = g_q + (((size_t)bh) * T + t0) * HS + d0;
                    *(float2*)dst            = make_float2(x0, x1);
                    *(float2*)(dst + 8 * HS) = make_float2(y0, y1);
                } else if (sel == 1) {
                    const int ktile = t0 >> 6;
                    const int kk  = d0 >> 4;
                    const int c   = d0 & 15;
                    const int tt  = (c & 7) >> 1;
                    const int hf  = c >> 3;
                    uint32_t* kp32 = (uint32_t*)g_kp;
                    size_t idx0 = ((((size_t)bh * 32 + ktile) * 4 + kk) * 256
                                  + ((size_t)((t0 >> 3) & 7)) * 32 + (t0 & 7) * 4 + tt);
                    kp32[idx0 * 2 + hf]        = h2(x0, x1);
                    kp32[(idx0 + 32) * 2 + hf] = h2(y0, y1);
                } else {
                    const int vtile = t0 >> 6;
                    const int kkv = (t0 & 63) >> 4;
                    const int gk  = t0 & 7;
                    const int ttv = gk >> 1;
                    const int kp  = gk & 1;
                    __half* vph = (__half*)g_vp;
                    size_t base = (((size_t)bh * 32 + vtile) * 4 + kkv) * 256;
                    size_t i_x0 = base + (size_t)(d0 >> 3) * 32 + (d0 & 7) * 4 + ttv;
                    size_t i_x1 = base + (size_t)((d0 + 1) >> 3) * 32 + ((d0 + 1) & 7) * 4 + ttv;
                    vph[i_x0 * 4 + kp]     = __float2half_rn(x0);
                    vph[i_x1 * 4 + kp]     = __float2half_rn(x1);
                    vph[i_x0 * 4 + 2 + kp] = __float2half_rn(y0);
                    vph[i_x1 * 4 + 2 + kp] = __float2half_rn(y1);
                }
            }
        }
    }
}

// ---------------- flash attention: 16 rows/warp, 4 CTAs/SM, diag n8-skip -----
#define ASTG 16384
#define ATTN_SMEM (3 * ASTG)   // 49152 B
#define ONE2 0x3C003C00u       // fp16 {1.0, 1.0}

__global__ __launch_bounds__(128, 4)
void attn_tc()
{
    extern __shared__ char smb[];

    const int qt   = gridDim.x - 1 - blockIdx.x;   // big tiles first
    const int h    = blockIdx.y;
    const int bb   = blockIdx.z;
    const int tid  = threadIdx.x;
    const int lane = tid & 31;
    const int warp = tid >> 5;
    const int g    = lane >> 2;
    const int t    = lane & 3;
    const int bh   = bb * NH + h;

    const float* qbase = g_q + ((size_t)bh * T + (size_t)qt * 64) * HS;

    // Q pre-scaled by (1/8)*log2(e): one m16 a-tile (rows warp*16 .. +15)
    const float SC = 0.125f * 1.44269504088896f;
    uint32_t qa[4][4];
    {
        const float* q0 = qbase + (size_t)(warp * 16 + g) * HS;
        const float* q1 = q0 + 8 * HS;
        #pragma unroll
        for (int kk = 0; kk < 4; kk++) {
            float2 v00 = *(const float2*)&q0[kk * 16 + 2 * t];
            float2 v10 = *(const float2*)&q1[kk * 16 + 2 * t];
            float2 v01 = *(const float2*)&q0[kk * 16 + 8 + 2 * t];
            float2 v11 = *(const float2*)&q1[kk * 16 + 8 + 2 * t];
            qa[kk][0] = h2(v00.x * SC, v00.y * SC);
            qa[kk][1] = h2(v10.x * SC, v10.y * SC);
            qa[kk][2] = h2(v01.x * SC, v01.y * SC);
            qa[kk][3] = h2(v11.x * SC, v11.y * SC);
        }
    }

    auto pref = [&](int s, int kt) {
        char* Kh = smb + s * ASTG;
        char* Vv = Kh + 8192;
        const char* kp = (const char*)(g_kp + ((size_t)bh * 32 + kt) * 1024);
        const char* vp = (const char*)(g_vp + ((size_t)bh * 32 + kt) * 1024);
        #pragma unroll
        for (int i = 0; i < 4; i++) {
            int o = (tid + i * 128) * 16;
            cp16b(Kh + o, kp + o);
            cp16b(Vv + o, vp + o);
        }
    };

    float4 O[8];
    float4 lacc = make_float4(0.f, 0.f, 0.f, 0.f);
    float  m0 = -1e30f, m1 = -1e30f;
    #pragma unroll
    for (int i = 0; i < 8; i++) O[i] = make_float4(0.f, 0.f, 0.f, 0.f);

    pref(0, 0); CP_COMMIT();
    if (qt > 0) { pref(1, 1); CP_COMMIT(); }

    for (int kt = 0; kt <= qt; kt++) {
        if (kt < qt) { CP_WAIT(1); } else { CP_WAIT(0); }
        __syncthreads();
        if (kt + 2 <= qt) { pref((kt + 2) % 3, kt + 2); CP_COMMIT(); }

        const uint2* Ksm = (const uint2*)(smb + (kt % 3) * ASTG);
        const uint2* Vsm = (const uint2*)(smb + (kt % 3) * ASTG + 8192);

        // diagonal tile: warp only needs key cols n8 <= 2*warp+1
        const bool diag = (kt == qt);
        const int n8max = diag ? (2 * warp + 2) : 8;

        // --- scores (log2 domain, fp32) ---
        float4 S[8];
        #pragma unroll
        for (int i = 0; i < 8; i++) S[i] = make_float4(0.f, 0.f, 0.f, 0.f);

        #pragma unroll
        for (int kk = 0; kk < 4; kk++) {
            #pragma unroll
            for (int n8 = 0; n8 < 8; n8++) {
                if (n8 < n8max) {
                    uint2 b = Ksm[(kk * 8 + n8) * 32 + lane];
                    mma_f16(S[n8], qa[kk][0], qa[kk][1], qa[kk][2], qa[kk][3], b.x, b.y);
                }
            }
        }

        // --- causal mask (only the diagonal tile) ---
        if (diag) {
            const int r0 = qt * 64 + warp * 16 + g;
            #pragma unroll
            for (int n8 = 0; n8 < 8; n8++) {
                if (n8 < n8max) {
                    int c0 = kt * 64 + n8 * 8 + 2 * t;
                    if (c0     > r0    ) S[n8].x = -1e30f;
                    if (c0 + 1 > r0    ) S[n8].y = -1e30f;
                    if (c0     > r0 + 8) S[n8].z = -1e30f;
                    if (c0 + 1 > r0 + 8) S[n8].w = -1e30f;
                } else {
                    S[n8] = make_float4(-1e30f, -1e30f, -1e30f, -1e30f);
                }
            }
        }

        // --- online softmax: P born as packed fp16 (h2exp2) ---
        float mx0 = -1e30f, mx1 = -1e30f;
        #pragma unroll
        for (int n8 = 0; n8 < 8; n8++) {
            mx0 = fmaxf(mx0, fmaxf(S[n8].x, S[n8].y));
            mx1 = fmaxf(mx1, fmaxf(S[n8].z, S[n8].w));
        }
        mx0 = fmaxf(mx0, __shfl_xor_sync(0xffffffffu, mx0, 1));
        mx0 = fmaxf(mx0, __shfl_xor_sync(0xffffffffu, mx0, 2));
        mx1 = fmaxf(mx1, __shfl_xor_sync(0xffffffffu, mx1, 1));
        mx1 = fmaxf(mx1, __shfl_xor_sync(0xffffffffu, mx1, 2));

        float nm0 = fmaxf(m0, mx0);
        float nm1 = fmaxf(m1, mx1);
        float c0 = exp2f(m0 - nm0);
        float c1 = exp2f(m1 - nm1);
        m0 = nm0; m1 = nm1;

        if (__any_sync(0xffffffffu, (c0 != 1.f) | (c1 != 1.f))) {
            lacc.x *= c0; lacc.z *= c1;
            #pragma unroll
            for (int n8 = 0; n8 < 8; n8++) {
                O[n8].x *= c0; O[n8].y *= c0;
                O[n8].z *= c1; O[n8].w *= c1;
            }
        }

        uint32_t pu[8][2];
        #pragma unroll
        for (int n8 = 0; n8 < 8; n8++) {
            if (n8 < n8max) {
                pu[n8][0] = h2exp2u(S[n8].x - nm0, S[n8].y - nm0);
                pu[n8][1] = h2exp2u(S[n8].z - nm1, S[n8].w - nm1);
            } else {
                pu[n8][0] = 0u;
                pu[n8][1] = 0u;
            }
        }

        // --- row sums via ones-MMA ---
        #pragma unroll
        for (int kk = 0; kk < 4; kk++) {
            if (2 * kk < n8max)
                mma_f16(lacc, pu[2*kk][0], pu[2*kk][1],
                        pu[2*kk+1][0], pu[2*kk+1][1], ONE2, ONE2);
        }

        // --- O += P V : C-frag -> A-frag identity ---
        #pragma unroll
        for (int kk = 0; kk < 4; kk++) {
            #pragma unroll
            for (int n8 = 0; n8 < 8; n8++) {
                uint2 b = Vsm[(kk * 8 + n8) * 32 + lane];
                if (2 * kk < n8max)
                    mma_f16(O[n8], pu[2*kk][0], pu[2*kk][1],
                            pu[2*kk+1][0], pu[2*kk+1][1], b.x, b.y);
            }
        }
    }

    // normalize + store into A-packed fp16 g_att
    {
        const float i0 = 1.0f / lacc.x;
        const float i1 = 1.0f / lacc.z;
        const int mtile = bb * 16 + (qt >> 1);
        const int m16   = (qt & 1) * 4 + warp;
        #pragma unroll
        for (int kk = 0; kk < 4; kk++) {
            uint4 u;
            u.x = h2(O[2 * kk].x * i0,     O[2 * kk].y * i0);
            u.y = h2(O[2 * kk].z * i1,     O[2 * kk].w * i1);
            u.z = h2(O[2 * kk + 1].x * i0, O[2 * kk + 1].y * i0);
            u.w = h2(O[2 * kk + 1].z * i1, O[2 * kk + 1].w * i1);
            g_att[(((size_t)mtile * 64 + h * 4 + kk) * 8 + m16) * 32 + lane] = u;
        }
    }
}

// ---------------------------------------------------------------------------
extern "C" void kernel_launch(void* const* d_in, const int* in_sizes, int n_in,
                              void* d_out, int out_size)
{
    const float* x  = (const float*)d_in[0];
    const float* Wq = (const float*)d_in[1];
    const float* bq = (const float*)d_in[2];
    const float* Wk = (const float*)d_in[3];
    const float* bk = (const float*)d_in[4];
    const float* Wv = (const float*)d_in[5];
    const float* bv = (const float*)d_in[6];
    const float* Wp = (const float*)d_in[7];
    const float* bp = (const float*)d_in[8];
    float* out = (float*)d_out;

    cudaFuncSetAttribute(gemm_tc<1>, cudaFuncAttributeMaxDynamicSharedMemorySize, GEMM_SMEM);
    cudaFuncSetAttribute(gemm_tc<0>, cudaFuncAttributeMaxDynamicSharedMemorySize, GEMM_SMEM);
    cudaFuncSetAttribute(attn_tc,    cudaFuncAttributeMaxDynamicSharedMemorySize, ATTN_SMEM);

    cvt_x<<<4096, 256>>>(x);
    wtr_all<<<4096, 256>>>(Wq, Wk, Wv, Wp);

    dim3 gq(24, M / 128);   // fused QKV
    gemm_tc<1><<<gq, 256, GEMM_SMEM>>>(bq, bk, bv, nullptr);

    dim3 ga(T / 64, NH, Bz);   // 32 x 16 x 4
    attn_tc<<<ga, 128, ATTN_SMEM>>>();

    dim3 gp(8, M / 128);
    gemm_tc<0><<<gp, 256, GEMM_SMEM>>>(bp, nullptr, nullptr, out);
}

// round 17
// speedup vs baseline: 1.1351x; 1.1351x over previous
#include <cuda_runtime.h>
#include <cuda_fp16.h>
#include <math.h>
#include <stdint.h>

#define Bz 4
#define T 2048
#define C 1024
#define NH 16
#define HS 64
#define M (Bz*T)

// ---------------- scratch (__device__ globals) -------------------------------
// A-pack (fp16 m16n8k16 A-frags): uint4[((mtile*64 + kk)*8 + m16)*32 + lane]
// B-pack (fp16 B-frags, n8-PAIRED): uint4[((ntile*64 + kk)*8 + n8p)*32 + lane]
//   uint4 = {b0(n8=2p), b1(n8=2p), b0(n8=2p+1), b1(n8=2p+1)}
// K/V-pack (attention B-frags, per b*h and 64-key tile):
//   uint2[(((bh*32 + tile)*4 + kk)*256) + n8*32 + lane]
__device__ uint4 g_x  [64*64*8*32];
__device__ uint4 g_att[64*64*8*32];
__device__ uint4 g_wq [8*64*8*32];
__device__ uint4 g_wk [8*64*8*32];
__device__ uint4 g_wv [8*64*8*32];
__device__ uint4 g_wp [8*64*8*32];
__device__ float  g_q[Bz*NH*T*HS];      // [B,NH,T,HS] fp32, RoPE'd
__device__ uint2  g_kp[64*32*1024];     // K packed (16 MB)
__device__ uint2  g_vp[64*32*1024];     // V packed (16 MB)

// ---------------- helpers ----------------------------------------------------
__device__ __forceinline__ uint32_t h2(float a, float b) {
    __half2 h = __floats2half2_rn(a, b);
    return *(uint32_t*)&h;
}
__device__ __forceinline__ uint32_t h2exp2u(float a, float b) {
    __half2 h = h2exp2(__floats2half2_rn(a, b));
    return *(uint32_t*)&h;
}

__device__ __forceinline__ void mma_f16(float4 &d,
    uint32_t a0, uint32_t a1, uint32_t a2, uint32_t a3,
    uint32_t b0, uint32_t b1)
{
    asm volatile(
        "mma.sync.aligned.m16n8k16.row.col.f32.f16.f16.f32 "
        "{%0,%1,%2,%3}, {%4,%5,%6,%7}, {%8,%9}, {%0,%1,%2,%3};\n"
        : "+f"(d.x), "+f"(d.y), "+f"(d.z), "+f"(d.w)
        : "r"(a0), "r"(a1), "r"(a2), "r"(a3), "r"(b0), "r"(b1));
}

__device__ __forceinline__ void cp16b(void* sdst, const void* gsrc) {
    uint32_t s = (uint32_t)__cvta_generic_to_shared(sdst);
    asm volatile("cp.async.cg.shared.global [%0], [%1], 16;" :: "r"(s), "l"(gsrc));
}
#define CP_COMMIT()  asm volatile("cp.async.commit_group;" ::: "memory")
#define CP_WAIT(N)   asm volatile("cp.async.wait_group %0;" :: "n"(N) : "memory")

// ---------------- prep: pack X into A-frag fp16 ------------------------------
__global__ void cvt_x(const float* __restrict__ x) {
    int idx = blockIdx.x * 256 + threadIdx.x;
    int lane = idx & 31, m16 = (idx >> 5) & 7, kk = (idx >> 8) & 63, mtile = idx >> 14;
    int g = lane >> 2, t = lane & 3;
    const float* p0 = x + (size_t)(mtile * 128 + m16 * 16 + g) * C + kk * 16 + 2 * t;
    const float* p1 = p0 + 8 * C;
    float2 v00 = *(const float2*)p0;
    float2 v10 = *(const float2*)p1;
    float2 v01 = *(const float2*)(p0 + 8);
    float2 v11 = *(const float2*)(p1 + 8);
    g_x[idx] = make_uint4(h2(v00.x, v00.y), h2(v10.x, v10.y),
                          h2(v01.x, v01.y), h2(v11.x, v11.y));
}

// ---------------- prep: pack all 4 W into paired B-frag fp16 -----------------
// one uint4 per (ntile, kk, n8p, lane): covers n8 = 2*n8p and 2*n8p+1
__global__ void wtr_all(const float* __restrict__ wq, const float* __restrict__ wk,
                        const float* __restrict__ wv, const float* __restrict__ wp)
{
    int sel = blockIdx.x >> 9;            // 512 blocks per matrix
    const float* w = (sel == 0) ? wq : (sel == 1) ? wk : (sel == 2) ? wv : wp;
    uint4* dst = (sel == 0) ? g_wq : (sel == 1) ? g_wk : (sel == 2) ? g_wv : g_wp;
    int idx = (blockIdx.x & 511) * 256 + threadIdx.x;   // 131072 per matrix
    int lane = idx & 31, n8p = (idx >> 5) & 7, kk = (idx >> 8) & 63, ntile = idx >> 14;
    int g = lane >> 2, t = lane & 3;
    int n = ntile * 128 + n8p * 16 + g;   // even n8 member; odd is n+8
    const float* p0 = w + (size_t)(kk * 16 + 2 * t) * C + n;
    const float* p1 = p0 + 8;
    dst[idx] = make_uint4(h2(p0[0], p0[C]), h2(p0[8 * C], p0[9 * C]),
                          h2(p1[0], p1[C]), h2(p1[8 * C], p1[9 * C]));
}

// ---------------- GEMM: fp16 k16, BK=64, 3-stage cp.async ring ---------------
#define GSTG 32768
#define GEMM_SMEM (3 * GSTG)   // 98304 B

template<int QKV>
__global__ __launch_bounds__(256, 2)
void gemm_tc(const float* __restrict__ b0p,
             const float* __restrict__ b1p,
             const float* __restrict__ b2p,
             float* __restrict__ outp)
{
    extern __shared__ char smb[];

    const uint4* Apk;
    const uint4* Bpk;
    const float* bias;
    int sel, ntile;
    if (QKV) {
        Apk = g_x;
        sel = blockIdx.x >> 3;
        ntile = blockIdx.x & 7;
        Bpk  = (sel == 0) ? g_wq : (sel == 1) ? g_wk : g_wv;
        bias = (sel == 0) ? b0p  : (sel == 1) ? b1p  : b2p;
    } else {
        Apk = g_att;
        sel = 3;
        ntile = blockIdx.x;
        Bpk = g_wp; bias = b0p;
    }
    const int mtile = blockIdx.y;
    const int tileM = mtile * 128;
    const int tileN = ntile * 128;

    const int tid   = threadIdx.x;
    const int lane  = tid & 31;
    const int warp  = tid >> 5;
    const int warpM = warp >> 2;
    const int warpN = warp & 3;
    const int g     = lane >> 2;
    const int t     = lane & 3;

    float4 acc[4][4];
    #pragma unroll
    for (int i = 0; i < 4; i++)
        #pragma unroll
        for (int j = 0; j < 4; j++)
            acc[i][j] = make_float4(0.f, 0.f, 0.f, 0.f);

    auto pref = [&](int s, int j) {
        char* As = smb + s * GSTG;
        char* Bs = As + 16384;
        const char* ap = (const char*)(Apk + ((size_t)mtile * 64 + 4 * j) * 256);
        const char* bp = (const char*)(Bpk + ((size_t)ntile * 64 + 4 * j) * 256);
        #pragma unroll
        for (int i = 0; i < 4; i++) {
            int o = (tid + i * 256) * 16;
            cp16b(As + o, ap + o);
            cp16b(Bs + o, bp + o);
        }
    };

    pref(0, 0); CP_COMMIT();
    pref(1, 1); CP_COMMIT();

    for (int j = 0; j < 16; j++) {
        if (j < 15) { CP_WAIT(1); } else { CP_WAIT(0); }
        __syncthreads();
        if (j + 2 < 16) { pref((j + 2) % 3, j + 2); CP_COMMIT(); }

        const uint4* As4 = (const uint4*)(smb + (j % 3) * GSTG);
        const uint4* Bs4 = (const uint4*)(smb + (j % 3) * GSTG + 16384);

        #pragma unroll
        for (int kk2 = 0; kk2 < 4; kk2++) {
            uint4 af[4];
            uint4 bv[2];
            #pragma unroll
            for (int mf = 0; mf < 4; mf++)
                af[mf] = As4[(kk2 * 8 + warpM * 4 + mf) * 32 + lane];
            #pragma unroll
            for (int nf2 = 0; nf2 < 2; nf2++)
                bv[nf2] = Bs4[(kk2 * 8 + warpN * 2 + nf2) * 32 + lane];
            #pragma unroll
            for (int mf = 0; mf < 4; mf++) {
                mma_f16(acc[mf][0], af[mf].x, af[mf].y, af[mf].z, af[mf].w,
                        bv[0].x, bv[0].y);
                mma_f16(acc[mf][1], af[mf].x, af[mf].y, af[mf].z, af[mf].w,
                        bv[0].z, bv[0].w);
                mma_f16(acc[mf][2], af[mf].x, af[mf].y, af[mf].z, af[mf].w,
                        bv[1].x, bv[1].y);
                mma_f16(acc[mf][3], af[mf].x, af[mf].y, af[mf].z, af[mf].w,
                        bv[1].z, bv[1].w);
            }
        }
    }

    // epilogue
    #pragma unroll
    for (int nf = 0; nf < 4; nf++) {
        const int n0 = tileN + warpN * 32 + nf * 8 + t * 2;
        const float bv0 = bias[n0];
        const float bv1 = bias[n0 + 1];
        float inv = 0.f;
        if (QKV) {
            const int ip = (n0 & 63) >> 1;
            inv = powf(10000.0f, -(float)ip / 32.0f);
        }
        #pragma unroll
        for (int mf = 0; mf < 4; mf++) {
            float4 a = acc[mf][nf];
            const int r0 = tileM + warpM * 64 + mf * 16 + g;
            float x0 = a.x + bv0, x1 = a.y + bv1;
            float y0 = a.z + bv0, y1 = a.w + bv1;
            if (!QKV) {
                *(float2*)&outp[(size_t)r0 * C + n0]       = make_float2(x0, x1);
                *(float2*)&outp[(size_t)(r0 + 8) * C + n0] = make_float2(y0, y1);
            } else {
                const int bb = r0 / T;
                const int t0 = r0 % T;
                const int h  = n0 >> 6;
                const int d0 = n0 & 63;
                const int bh = bb * NH + h;
                if (sel < 2) {
                    float sn, cs;
                    sincosf((float)t0 * inv, &sn, &cs);
                    float u0 = x0 * cs - x1 * sn;
                    float u1 = x0 * sn + x1 * cs;
                    x0 = u0; x1 = u1;
                    sincosf((float)(t0 + 8) * inv, &sn, &cs);
                    float w0 = y0 * cs - y1 * sn;
                    float w1 = y0 * sn + y1 * cs;
                    y0 = w0; y1 = w1;
                }
                if (sel == 0) {
                    float* dst = g_q + (((size_t)bh) * T + t0) * HS + d0;
                    *(float2*)dst            = make_float2(x0, x1);
                    *(float2*)(dst + 8 * HS) = make_float2(y0, y1);
                } else if (sel == 1) {
                    const int ktile = t0 >> 6;
                    const int kk  = d0 >> 4;
                    const int c   = d0 & 15;
                    const int tt  = (c & 7) >> 1;
                    const int hf  = c >> 3;
                    uint32_t* kp32 = (uint32_t*)g_kp;
                    size_t idx0 = ((((size_t)bh * 32 + ktile) * 4 + kk) * 256
                                  + ((size_t)((t0 >> 3) & 7)) * 32 + (t0 & 7) * 4 + tt);
                    kp32[idx0 * 2 + hf]        = h2(x0, x1);
                    kp32[(idx0 + 32) * 2 + hf] = h2(y0, y1);
                } else {
                    const int vtile = t0 >> 6;
                    const int kkv = (t0 & 63) >> 4;
                    const int gk  = t0 & 7;
                    const int ttv = gk >> 1;
                    const int kp  = gk & 1;
                    __half* vph = (__half*)g_vp;
                    size_t base = (((size_t)bh * 32 + vtile) * 4 + kkv) * 256;
                    size_t i_x0 = base + (size_t)(d0 >> 3) * 32 + (d0 & 7) * 4 + ttv;
                    size_t i_x1 = base + (size_t)((d0 + 1) >> 3) * 32 + ((d0 + 1) & 7) * 4 + ttv;
                    vph[i_x0 * 4 + kp]     = __float2half_rn(x0);
                    vph[i_x1 * 4 + kp]     = __float2half_rn(x1);
                    vph[i_x0 * 4 + 2 + kp] = __float2half_rn(y0);
                    vph[i_x1 * 4 + 2 + kp] = __float2half_rn(y1);
                }
            }
        }
    }
}

// ---------------- flash attention: 16 rows/warp, 64 rows/block, 3 CTAs/SM ----
// (round-15 proven version, verbatim)
#define ASTG 16384
#define ATTN_SMEM (3 * ASTG)   // 49152 B
#define ONE2 0x3C003C00u       // fp16 {1.0, 1.0}

__global__ __launch_bounds__(128, 3)
void attn_tc()
{
    extern __shared__ char smb[];

    const int qt   = gridDim.x - 1 - blockIdx.x;   // big tiles first
    const int h    = blockIdx.y;
    const int bb   = blockIdx.z;
    const int tid  = threadIdx.x;
    const int lane = tid & 31;
    const int warp = tid >> 5;
    const int g    = lane >> 2;
    const int t    = lane & 3;
    const int bh   = bb * NH + h;

    const float* qbase = g_q + ((size_t)bh * T + (size_t)qt * 64) * HS;

    // Q pre-scaled by (1/8)*log2(e): one m16 a-tile (rows warp*16 .. +15)
    const float SC = 0.125f * 1.44269504088896f;
    uint32_t qa[4][4];
    {
        const float* q0 = qbase + (size_t)(warp * 16 + g) * HS;
        const float* q1 = q0 + 8 * HS;
        #pragma unroll
        for (int kk = 0; kk < 4; kk++) {
            float2 v00 = *(const float2*)&q0[kk * 16 + 2 * t];
            float2 v10 = *(const float2*)&q1[kk * 16 + 2 * t];
            float2 v01 = *(const float2*)&q0[kk * 16 + 8 + 2 * t];
            float2 v11 = *(const float2*)&q1[kk * 16 + 8 + 2 * t];
            qa[kk][0] = h2(v00.x * SC, v00.y * SC);
            qa[kk][1] = h2(v10.x * SC, v10.y * SC);
            qa[kk][2] = h2(v01.x * SC, v01.y * SC);
            qa[kk][3] = h2(v11.x * SC, v11.y * SC);
        }
    }

    auto pref = [&](int s, int kt) {
        char* Kh = smb + s * ASTG;
        char* Vv = Kh + 8192;
        const char* kp = (const char*)(g_kp + ((size_t)bh * 32 + kt) * 1024);
        const char* vp = (const char*)(g_vp + ((size_t)bh * 32 + kt) * 1024);
        #pragma unroll
        for (int i = 0; i < 4; i++) {
            int o = (tid + i * 128) * 16;
            cp16b(Kh + o, kp + o);
            cp16b(Vv + o, vp + o);
        }
    };

    float4 O[8];
    float4 lacc = make_float4(0.f, 0.f, 0.f, 0.f);
    float  m0 = -1e30f, m1 = -1e30f;
    #pragma unroll
    for (int i = 0; i < 8; i++) O[i] = make_float4(0.f, 0.f, 0.f, 0.f);

    pref(0, 0); CP_COMMIT();
    if (qt > 0) { pref(1, 1); CP_COMMIT(); }

    for (int kt = 0; kt <= qt; kt++) {
        if (kt < qt) { CP_WAIT(1); } else { CP_WAIT(0); }
        __syncthreads();
        if (kt + 2 <= qt) { pref((kt + 2) % 3, kt + 2); CP_COMMIT(); }

        const uint2* Ksm = (const uint2*)(smb + (kt % 3) * ASTG);
        const uint2* Vsm = (const uint2*)(smb + (kt % 3) * ASTG + 8192);

        // --- scores (log2 domain, fp32) ---
        float4 S[8];
        #pragma unroll
        for (int i = 0; i < 8; i++) S[i] = make_float4(0.f, 0.f, 0.f, 0.f);

        #pragma unroll
        for (int kk = 0; kk < 4; kk++) {
            #pragma unroll
            for (int n8 = 0; n8 < 8; n8++) {
                uint2 b = Ksm[(kk * 8 + n8) * 32 + lane];
                mma_f16(S[n8], qa[kk][0], qa[kk][1], qa[kk][2], qa[kk][3], b.x, b.y);
            }
        }

        // --- causal mask (only the diagonal tile) ---
        if (kt == qt) {
            const int r0 = qt * 64 + warp * 16 + g;
            #pragma unroll
            for (int n8 = 0; n8 < 8; n8++) {
                int c0 = kt * 64 + n8 * 8 + 2 * t;
                if (c0     > r0    ) S[n8].x = -1e30f;
                if (c0 + 1 > r0    ) S[n8].y = -1e30f;
                if (c0     > r0 + 8) S[n8].z = -1e30f;
                if (c0 + 1 > r0 + 8) S[n8].w = -1e30f;
            }
        }

        // --- online softmax: P born as packed fp16 (h2exp2) ---
        float mx0 = -1e30f, mx1 = -1e30f;
        #pragma unroll
        for (int n8 = 0; n8 < 8; n8++) {
            mx0 = fmaxf(mx0, fmaxf(S[n8].x, S[n8].y));
            mx1 = fmaxf(mx1, fmaxf(S[n8].z, S[n8].w));
        }
        mx0 = fmaxf(mx0, __shfl_xor_sync(0xffffffffu, mx0, 1));
        mx0 = fmaxf(mx0, __shfl_xor_sync(0xffffffffu, mx0, 2));
        mx1 = fmaxf(mx1, __shfl_xor_sync(0xffffffffu, mx1, 1));
        mx1 = fmaxf(mx1, __shfl_xor_sync(0xffffffffu, mx1, 2));

        float nm0 = fmaxf(m0, mx0);
        float nm1 = fmaxf(m1, mx1);
        float c0 = exp2f(m0 - nm0);
        float c1 = exp2f(m1 - nm1);
        m0 = nm0; m1 = nm1;

        if (__any_sync(0xffffffffu, (c0 != 1.f) | (c1 != 1.f))) {
            lacc.x *= c0; lacc.z *= c1;
            #pragma unroll
            for (int n8 = 0; n8 < 8; n8++) {
                O[n8].x *= c0; O[n8].y *= c0;
                O[n8].z *= c1; O[n8].w *= c1;
            }
        }

        uint32_t pu[8][2];
        #pragma unroll
        for (int n8 = 0; n8 < 8; n8++) {
            pu[n8][0] = h2exp2u(S[n8].x - nm0, S[n8].y - nm0);
            pu[n8][1] = h2exp2u(S[n8].z - nm1, S[n8].w - nm1);
        }

        // --- row sums via ones-MMA ---
        #pragma unroll
        for (int kk = 0; kk < 4; kk++)
            mma_f16(lacc, pu[2*kk][0], pu[2*kk][1],
                    pu[2*kk+1][0], pu[2*kk+1][1], ONE2, ONE2);

        // --- O += P V : C-frag -> A-frag identity ---
        #pragma unroll
        for (int kk = 0; kk < 4; kk++) {
            #pragma unroll
            for (int n8 = 0; n8 < 8; n8++) {
                uint2 b = Vsm[(kk * 8 + n8) * 32 + lane];
                mma_f16(O[n8], pu[2*kk][0], pu[2*kk][1],
                        pu[2*kk+1][0], pu[2*kk+1][1], b.x, b.y);
            }
        }
    }

    // normalize + store into A-packed fp16 g_att
    {
        const float i0 = 1.0f / lacc.x;
        const float i1 = 1.0f / lacc.z;
        const int mtile = bb * 16 + (qt >> 1);
        const int m16   = (qt & 1) * 4 + warp;
        #pragma unroll
        for (int kk = 0; kk < 4; kk++) {
            uint4 u;
            u.x = h2(O[2 * kk].x * i0,     O[2 * kk].y * i0);
            u.y = h2(O[2 * kk].z * i1,     O[2 * kk].w * i1);
            u.z = h2(O[2 * kk + 1].x * i0, O[2 * kk + 1].y * i0);
            u.w = h2(O[2 * kk + 1].z * i1, O[2 * kk + 1].w * i1);
            g_att[(((size_t)mtile * 64 + h * 4 + kk) * 8 + m16) * 32 + lane] = u;
        }
    }
}

// ---------------------------------------------------------------------------
extern "C" void kernel_launch(void* const* d_in, const int* in_sizes, int n_in,
                              void* d_out, int out_size)
{
    const float* x  = (const float*)d_in[0];
    const float* Wq = (const float*)d_in[1];
    const float* bq = (const float*)d_in[2];
    const float* Wk = (const float*)d_in[3];
    const float* bk = (const float*)d_in[4];
    const float* Wv = (const float*)d_in[5];
    const float* bv = (const float*)d_in[6];
    const float* Wp = (const float*)d_in[7];
    const float* bp = (const float*)d_in[8];
    float* out = (float*)d_out;

    cudaFuncSetAttribute(gemm_tc<1>, cudaFuncAttributeMaxDynamicSharedMemorySize, GEMM_SMEM);
    cudaFuncSetAttribute(gemm_tc<0>, cudaFuncAttributeMaxDynamicSharedMemorySize, GEMM_SMEM);
    cudaFuncSetAttribute(attn_tc,    cudaFuncAttributeMaxDynamicSharedMemorySize, ATTN_SMEM);

    cvt_x<<<4096, 256>>>(x);
    wtr_all<<<2048, 256>>>(Wq, Wk, Wv, Wp);

    dim3 gq(24, M / 128);   // fused QKV
    gemm_tc<1><<<gq, 256, GEMM_SMEM>>>(bq, bk, bv, nullptr);

    dim3 ga(T / 64, NH, Bz);   // 32 x 16 x 4
    attn_tc<<<ga, 128, ATTN_SMEM>>>();

    dim3 gp(8, M / 128);
    gemm_tc<0><<<gp, 256, GEMM_SMEM>>>(bp, nullptr, nullptr, out);
}